// round 10
// baseline (speedup 1.0000x reference)
#include <cuda_runtime.h>
#include <cuda_fp16.h>
#include <math.h>
#include <stdint.h>

#define KNOTS   16
#define BOUNDV  5.0f
#define XDIM    6
#define CDIM    4
#define HID     128
#define SPLD    47
#define LOWERD  3
#define OUTD    141
#define N3PAD   160      // GEMM3 n padded to 4*40
#define MROWS   128
#define NTHREADS 256

#define AST   136   // A tile stride (halves)
#define W2ST  136
#define W3ST  168
#define PST   147   // P stride (floats)

// ---- smem byte offsets ----
#define OFF_AH   0                     // 34816  Ah fp16 [128][136]
#define OFF_AL   34816                 // 34816  Al fp16 [128][136]
#define OFF_WP   69632                 // pool: W2 (34816) + W3 (43008) -> later P (75264)
#define OFF_W2   69632
#define OFF_W3   104448
#define OFF_P    69632
#define OFF_IN   147456                // 4096
#define OFF_LOW  151552                // 2048
#define OFF_W1   153600                // 3584
#define OFF_B1   157184                // 512
#define OFF_B2   157696                // 512
#define OFF_B3   158208                // 640 (160 floats)
#define OFF_LD   158848                // 2048
#define SMEM_BYTES 160896

static __device__ __forceinline__ uint32_t smem_u32(const void* p) {
    uint32_t a;
    asm("{ .reg .u64 t; cvta.to.shared.u64 t, %1; cvt.u32.u64 %0, t; }" : "=r"(a) : "l"(p));
    return a;
}

static __device__ __forceinline__ void ldsm_x4(uint32_t a, uint32_t& r0, uint32_t& r1,
                                               uint32_t& r2, uint32_t& r3) {
    asm volatile("ldmatrix.sync.aligned.m8n8.x4.shared.b16 {%0,%1,%2,%3}, [%4];"
                 : "=r"(r0), "=r"(r1), "=r"(r2), "=r"(r3) : "r"(a));
}
static __device__ __forceinline__ void ldsm_x4t(uint32_t a, uint32_t& r0, uint32_t& r1,
                                                uint32_t& r2, uint32_t& r3) {
    asm volatile("ldmatrix.sync.aligned.m8n8.x4.trans.shared.b16 {%0,%1,%2,%3}, [%4];"
                 : "=r"(r0), "=r"(r1), "=r"(r2), "=r"(r3) : "r"(a));
}
static __device__ __forceinline__ void ldsm_x2t(uint32_t a, uint32_t& r0, uint32_t& r1) {
    asm volatile("ldmatrix.sync.aligned.m8n8.x2.trans.shared.b16 {%0,%1}, [%2];"
                 : "=r"(r0), "=r"(r1) : "r"(a));
}
static __device__ __forceinline__ void mma16816(float* c, const uint32_t* a,
                                                uint32_t b0, uint32_t b1) {
    asm volatile("mma.sync.aligned.m16n8k16.row.col.f32.f16.f16.f32 "
                 "{%0,%1,%2,%3}, {%4,%5,%6,%7}, {%8,%9}, {%0,%1,%2,%3};"
                 : "+f"(c[0]), "+f"(c[1]), "+f"(c[2]), "+f"(c[3])
                 : "r"(a[0]), "r"(a[1]), "r"(a[2]), "r"(a[3]), "r"(b0), "r"(b1));
}

// ---- FFMA-pipe exp (valid for x <= ~0; clamps hard underflow) ----
static __device__ __forceinline__ float fexp(float x) {
    float t = x * 1.4426950408889634f;
    t = fmaxf(t, -125.0f);
    float r = t + 12582912.0f;
    float fi = r - 12582912.0f;
    float f = t - fi;
    int i = (int)fi;
    float p = 1.5403530393e-4f;
    p = fmaf(p, f, 1.3333558146e-3f);
    p = fmaf(p, f, 9.6181291076e-3f);
    p = fmaf(p, f, 5.5504108664e-2f);
    p = fmaf(p, f, 2.4022650696e-1f);
    p = fmaf(p, f, 6.9314718056e-1f);
    p = fmaf(p, f, 1.0f);
    return __int_as_float(__float_as_int(p) + (i << 23));
}

// ---- FFMA-pipe natural log (u > 0, normal) ----
static __device__ __forceinline__ float flog(float u) {
    int ib = __float_as_int(u);
    int e = (ib - 0x3f3504f3) >> 23;
    float m = __int_as_float(ib - (e << 23));
    float f = m - 1.0f;
    float z = f * f;
    float P = 7.0376836292e-2f;
    P = fmaf(P, f, -1.1514610310e-1f);
    P = fmaf(P, f, 1.1676998740e-1f);
    P = fmaf(P, f, -1.2420140846e-1f);
    P = fmaf(P, f, 1.4249322787e-1f);
    P = fmaf(P, f, -1.6668057665e-1f);
    P = fmaf(P, f, 2.0000714765e-1f);
    P = fmaf(P, f, -2.4999993993e-1f);
    P = fmaf(P, f, 3.3333331174e-1f);
    float rr = fmaf(P * z, f, fmaf(-0.5f, z, f));
    return fmaf((float)e, 0.69314718055994531f, rr);
}

static __device__ __forceinline__ float softplus_f(float v) {
    return fmaxf(v, 0.0f) + flog(1.0f + fexp(-fabsf(v)));
}

__global__ __launch_bounds__(NTHREADS, 1)
void nsc_hmma_kernel(const float* __restrict__ x, const float* __restrict__ c,
                     const float* __restrict__ W1, const float* __restrict__ b1,
                     const float* __restrict__ W2, const float* __restrict__ b2,
                     const float* __restrict__ W3, const float* __restrict__ b3,
                     float* __restrict__ out, int B, int ntiles)
{
    extern __shared__ char smb[];
    const uint32_t sb = smem_u32(smb);

    __half* hAh = (__half*)(smb + OFF_AH);
    __half* hAl = (__half*)(smb + OFF_AL);
    __half* hW2 = (__half*)(smb + OFF_W2);
    __half* hW3 = (__half*)(smb + OFF_W3);
    float* sP   = (float*)(smb + OFF_P);
    float* sIn  = (float*)(smb + OFF_IN);
    float* sLow = (float*)(smb + OFF_LOW);
    float* sW1  = (float*)(smb + OFF_W1);
    float* sB1  = (float*)(smb + OFF_B1);
    float* sB2  = (float*)(smb + OFF_B2);
    float* sB3  = (float*)(smb + OFF_B3);
    float* sLd  = (float*)(smb + OFF_LD);

    const int tid = threadIdx.x;
    const int warp = tid >> 5;          // 0..7
    const int lane = tid & 31;
    const int wm2 = warp >> 2;          // 0..1 -> m0 = wm2*64
    const int wn4 = warp & 3;           // 0..3
    const int m0 = wm2 * 64;
    const int n0g2 = wn4 * 32;
    const int n0g3 = wn4 * 40;
    const int lr = lane & 15;
    const int lc = (lane >> 4) * 8;
    const int grow = lane >> 2;
    const int gcol = (lane & 3) * 2;

    // ---- one-time weight staging into SMEM ----
    for (int i = tid; i < HID * HID; i += NTHREADS) {
        int k = i >> 7, n = i & 127;
        hW2[k * W2ST + n] = __float2half_rn(W2[i]);
    }
    for (int i = tid; i < HID * W3ST; i += NTHREADS) {
        int k = i / W3ST, n = i - k * W3ST;
        hW3[i] = __float2half_rn((n < OUTD) ? W3[k * OUTD + n] : 0.0f);
    }
    for (int i = tid; i < 7 * HID; i += NTHREADS) sW1[i] = W1[i];
    if (tid < HID) { sB1[tid] = b1[tid]; sB2[tid] = b2[tid]; }
    if (tid < N3PAD) sB3[tid] = (tid < OUTD) ? b3[tid] : 0.0f;
    __syncthreads();

    // ---- one-time: persistent B fragments in registers ----
    uint32_t B2f[8][8];    // [kblk][n8blk*2 + {b0,b1}]
    uint32_t B3f[8][10];
    #pragma unroll
    for (int ki = 0; ki < 8; ki++) {
        const int kb = ki * 16;
        #pragma unroll
        for (int np = 0; np < 2; np++) {
            uint32_t boff = (uint32_t)(((kb + lr) * W2ST + n0g2 + np * 16 + lc) * 2);
            ldsm_x4t(sb + OFF_W2 + boff, B2f[ki][np*4], B2f[ki][np*4+1],
                     B2f[ki][np*4+2], B2f[ki][np*4+3]);
        }
        #pragma unroll
        for (int np = 0; np < 2; np++) {
            uint32_t boff = (uint32_t)(((kb + lr) * W3ST + n0g3 + np * 16 + lc) * 2);
            ldsm_x4t(sb + OFF_W3 + boff, B3f[ki][np*4], B3f[ki][np*4+1],
                     B3f[ki][np*4+2], B3f[ki][np*4+3]);
        }
        {
            uint32_t boff = (uint32_t)(((kb + lr) * W3ST + n0g3 + 32) * 2);
            ldsm_x2t(sb + OFF_W3 + boff, B3f[ki][8], B3f[ki][9]);
        }
    }
    __syncthreads();   // W SMEM now dead -> reused as P

    for (long tile = blockIdx.x; tile < ntiles; tile += gridDim.x) {
        const long base = tile * MROWS;
        const int nrows = (int)min((long)MROWS, (long)B - base);
        __syncthreads();

        // ---- stage inputs ----
        for (int i = tid; i < MROWS * XDIM; i += NTHREADS) {
            int r = i / XDIM, cc = i - r * XDIM;
            float v = (r < nrows) ? x[(base + r) * XDIM + cc] : 0.0f;
            if (cc < LOWERD) sLow[r * 4 + cc] = v;
            else             sIn[r * 8 + (cc - LOWERD)] = v;
        }
        for (int i = tid; i < MROWS * CDIM; i += NTHREADS) {
            int r = i >> 2, cc = i & 3;
            sIn[r * 8 + 3 + cc] = (r < nrows) ? c[(base + r) * CDIM + cc] : 0.0f;
        }
        __syncthreads();

        // ---- layer 1 (fp32) -> split fp16 A ----
        for (int t = tid; t < MROWS * 64; t += NTHREADS) {
            int r = t >> 6, np = (t & 63) << 1;
            float a0 = sB1[np], a1 = sB1[np + 1];
            const float* inr = &sIn[r * 8];
            #pragma unroll
            for (int k = 0; k < 7; k++) {
                float iv = inr[k];
                a0 = fmaf(iv, sW1[k * HID + np], a0);
                a1 = fmaf(iv, sW1[k * HID + np + 1], a1);
            }
            a0 = fmaxf(a0, 0.0f); a1 = fmaxf(a1, 0.0f);
            __half h0 = __float2half_rn(a0), h1v = __float2half_rn(a1);
            __half l0 = __float2half_rn(a0 - __half2float(h0));
            __half l1 = __float2half_rn(a1 - __half2float(h1v));
            *(__half2*)&hAh[r * AST + np] = __halves2half2(h0, h1v);
            *(__half2*)&hAl[r * AST + np] = __halves2half2(l0, l1);
        }
        __syncthreads();

        // ---- GEMM2: 128x128x128, split-A, warp tile 64x32, B in regs ----
        float acc2[4][4][4];
        #pragma unroll
        for (int ms = 0; ms < 4; ms++)
            #pragma unroll
            for (int nb = 0; nb < 4; nb++)
                #pragma unroll
                for (int q = 0; q < 4; q++) acc2[ms][nb][q] = 0.0f;
        #pragma unroll
        for (int ki = 0; ki < 8; ki++) {
            const int kb = ki * 16;
            #pragma unroll
            for (int ms = 0; ms < 4; ms++) {
                uint32_t ah[4], al[4];
                uint32_t aoff = (uint32_t)(((m0 + ms * 16 + lr) * AST + kb + lc) * 2);
                ldsm_x4(sb + OFF_AH + aoff, ah[0], ah[1], ah[2], ah[3]);
                ldsm_x4(sb + OFF_AL + aoff, al[0], al[1], al[2], al[3]);
                #pragma unroll
                for (int nb = 0; nb < 4; nb++) {
                    mma16816(acc2[ms][nb], ah, B2f[ki][nb*2], B2f[ki][nb*2+1]);
                    mma16816(acc2[ms][nb], al, B2f[ki][nb*2], B2f[ki][nb*2+1]);
                }
            }
        }
        __syncthreads();

        // ---- h2 = relu(D + b2) -> plain fp16 A (overwrite hi buffer) ----
        #pragma unroll
        for (int ms = 0; ms < 4; ms++)
            #pragma unroll
            for (int nb = 0; nb < 4; nb++) {
                int col = n0g2 + nb * 8 + gcol;
                float bb0 = sB2[col], bb1 = sB2[col + 1];
                #pragma unroll
                for (int h = 0; h < 2; h++) {
                    int r = m0 + ms * 16 + grow + h * 8;
                    float v0 = fmaxf(acc2[ms][nb][2*h]   + bb0, 0.0f);
                    float v1 = fmaxf(acc2[ms][nb][2*h+1] + bb1, 0.0f);
                    *(__half2*)&hAh[r * AST + col] =
                        __halves2half2(__float2half_rn(v0), __float2half_rn(v1));
                }
            }
        __syncthreads();

        // ---- GEMM3: 128x160x128, plain-A, warp tile 64x40, B in regs ----
        {
            float acc3[4][5][4];
            #pragma unroll
            for (int ms = 0; ms < 4; ms++)
                #pragma unroll
                for (int nb = 0; nb < 5; nb++)
                    #pragma unroll
                    for (int q = 0; q < 4; q++) acc3[ms][nb][q] = 0.0f;
            #pragma unroll
            for (int ki = 0; ki < 8; ki++) {
                const int kb = ki * 16;
                #pragma unroll
                for (int ms = 0; ms < 4; ms++) {
                    uint32_t ah[4];
                    uint32_t aoff = (uint32_t)(((m0 + ms * 16 + lr) * AST + kb + lc) * 2);
                    ldsm_x4(sb + OFF_AH + aoff, ah[0], ah[1], ah[2], ah[3]);
                    #pragma unroll
                    for (int nb = 0; nb < 5; nb++)
                        mma16816(acc3[ms][nb], ah, B3f[ki][nb*2], B3f[ki][nb*2+1]);
                }
            }
            // P = D + b3 (skip pad cols >= 144)
            #pragma unroll
            for (int ms = 0; ms < 4; ms++)
                #pragma unroll
                for (int nb = 0; nb < 5; nb++) {
                    int col = n0g3 + nb * 8 + gcol;
                    if (col < 144) {
                        float bb0 = sB3[col], bb1 = sB3[col + 1];
                        #pragma unroll
                        for (int h = 0; h < 2; h++) {
                            int r = m0 + ms * 16 + grow + h * 8;
                            sP[r * PST + col]     = acc3[ms][nb][2*h]   + bb0;
                            sP[r * PST + col + 1] = acc3[ms][nb][2*h+1] + bb1;
                        }
                    }
                }
        }
        __syncthreads();

        // ---- spline epilogue (FFMA-pipe transcendentals) ----
        for (int item = tid; item < MROWS * LOWERD; item += NTHREADS) {
            const int r = item / 3;
            const int d = item - r * 3;
            const float* p = &sP[r * PST + d * SPLD];
            const float xv = sLow[r * 4 + d];
            const bool oob = (xv <= -BOUNDV) || (xv >= BOUNDV);
            const float xm = oob ? -BOUNDV : xv;

            float mW = -1e30f;
            #pragma unroll
            for (int i = 0; i < KNOTS; i++) mW = fmaxf(mW, p[i]);
            float ew[KNOTS], S = 0.0f;
            #pragma unroll
            for (int i = 0; i < KNOTS; i++) { ew[i] = fexp(p[i] - mW); S += ew[i]; }
            const float invS = __fdividef(2.0f * BOUNDV, S);

            int idx = 0; float cumex = 0.0f, wsel = ew[0];
            bool found = false; float cum = 0.0f;
            #pragma unroll
            for (int i = 0; i < KNOTS; i++) {
                float cn = cum + ew[i];
                bool take = (!found) && (xm < fmaf(cn, invS, -BOUNDV));
                if (take) { found = true; idx = i; cumex = cum; wsel = ew[i]; }
                cum = cn;
            }
            if (!found) { idx = KNOTS - 1; cumex = cum - ew[KNOTS - 1]; wsel = ew[KNOTS - 1]; }

            const float xk_b = fmaf(cumex, invS, -BOUNDV);
            const float wk   = wsel * invS;

            float mH = -1e30f;
            #pragma unroll
            for (int i = 0; i < KNOTS; i++) mH = fmaxf(mH, p[KNOTS + i]);
            float SH = 0.0f, cumh = 0.0f, hsel = 0.0f;
            #pragma unroll
            for (int i = 0; i < KNOTS; i++) {
                float e = fexp(p[KNOTS + i] - mH);
                SH += e;
                if (i < idx)  cumh += e;
                if (i == idx) hsel = e;
            }
            const float invSH = __fdividef(2.0f * BOUNDV, SH);
            const float yk_b = fmaf(cumh, invSH, -BOUNDV);
            const float hk   = hsel * invSH;

            float d0 = 1.0f, d1 = 1.0f;
            if (idx > 0)         d0 = softplus_f(p[2 * KNOTS + idx - 1]);
            if (idx < KNOTS - 1) d1 = softplus_f(p[2 * KNOTS + idx]);

            const float rwk = __fdividef(1.0f, wk);
            const float sk = hk * rwk;
            float relx = fminf(fmaxf((xm - xk_b) * rwk, 0.0f), 1.0f);
            const float omr = 1.0f - relx;
            const float r1 = relx * omr;
            const float den = sk + (d1 + d0 - 2.0f * sk) * r1;
            const float rden = __fdividef(1.0f, den);
            const float num = hk * (sk * relx * relx + d0 * r1);
            float y = yk_b + num * rden;
            const float arg = d1 * relx * relx + 2.0f * sk * r1 + d0 * omr * omr;
            float ld = flog(sk * sk * arg * rden * rden);
            if (oob) { y = xv; ld = 0.0f; }

            sLd[r * 4 + d] = ld;
            if (r < nrows) {
                out[(base + r) * XDIM + d] = y;
                out[(base + r) * XDIM + LOWERD + d] = sIn[r * 8 + d];
            }
        }
        __syncthreads();
        if (tid < MROWS && tid < nrows)
            out[(long)B * XDIM + base + tid] =
                sLd[tid * 4] + sLd[tid * 4 + 1] + sLd[tid * 4 + 2];
    }
}

extern "C" void kernel_launch(void* const* d_in, const int* in_sizes, int n_in,
                              void* d_out, int out_size)
{
    const float* x  = (const float*)d_in[0];
    const float* c  = (const float*)d_in[1];
    const float* W1 = (const float*)d_in[2];
    const float* b1 = (const float*)d_in[3];
    const float* W2 = (const float*)d_in[4];
    const float* b2 = (const float*)d_in[5];
    const float* W3 = (const float*)d_in[6];
    const float* b3 = (const float*)d_in[7];
    (void)n_in; (void)out_size;

    const int B = in_sizes[0] / XDIM;
    const int ntiles = (B + MROWS - 1) / MROWS;
    float* out = (float*)d_out;

    int sms = 148;
    cudaDeviceGetAttribute(&sms, cudaDevAttrMultiProcessorCount, 0);
    int grid = sms < ntiles ? sms : ntiles;

    cudaFuncSetAttribute(nsc_hmma_kernel, cudaFuncAttributeMaxDynamicSharedMemorySize,
                         SMEM_BYTES);
    nsc_hmma_kernel<<<grid, NTHREADS, SMEM_BYTES>>>(x, c, W1, b1, W2, b2, W3, b3,
                                                    out, B, ntiles);
}

// round 11
// speedup vs baseline: 1.0845x; 1.0845x over previous
#include <cuda_runtime.h>
#include <cuda_fp16.h>
#include <math.h>
#include <stdint.h>

#define KNOTS   16
#define BOUNDV  5.0f
#define XDIM    6
#define CDIM    4
#define HID     128
#define SPLD    47
#define LOWERD  3
#define OUTD    141
#define N3PAD   160
#define MROWS   128
#define NTHREADS 512

#define AST   136   // A tile stride (halves)
#define W2ST  136
#define W3ST  168   // 160 + 8 pad (halves)
#define PST   147   // P stride (floats)

// ---- smem byte offsets ----
#define OFF_AH   0                     // 34816  Ah fp16 [128][136]
#define OFF_AL   34816                 // 34816  Al fp16 [128][136]
#define OFF_W3   69632                 // 43008  W3 fp16 [128][168]
#define OFF_P    112640                // 75264  P fp32 [128][147]
#define OFF_W2   112640                // W2 staged temporarily in P region
#define OFF_IN   187904                // 4096
#define OFF_LOW  192000                // 2048
#define OFF_W1   194048                // 3584
#define OFF_B1   197632                // 512
#define OFF_B2   198144                // 512
#define OFF_B3   198656                // 640 (160 floats)
#define OFF_LD   199296                // 2048
#define SMEM_BYTES 201472

static __device__ __forceinline__ uint32_t smem_u32(const void* p) {
    uint32_t a;
    asm("{ .reg .u64 t; cvta.to.shared.u64 t, %1; cvt.u32.u64 %0, t; }" : "=r"(a) : "l"(p));
    return a;
}

static __device__ __forceinline__ void ldsm_x4(uint32_t a, uint32_t& r0, uint32_t& r1,
                                               uint32_t& r2, uint32_t& r3) {
    asm volatile("ldmatrix.sync.aligned.m8n8.x4.shared.b16 {%0,%1,%2,%3}, [%4];"
                 : "=r"(r0), "=r"(r1), "=r"(r2), "=r"(r3) : "r"(a));
}
static __device__ __forceinline__ void ldsm_x4t(uint32_t a, uint32_t& r0, uint32_t& r1,
                                                uint32_t& r2, uint32_t& r3) {
    asm volatile("ldmatrix.sync.aligned.m8n8.x4.trans.shared.b16 {%0,%1,%2,%3}, [%4];"
                 : "=r"(r0), "=r"(r1), "=r"(r2), "=r"(r3) : "r"(a));
}
static __device__ __forceinline__ void ldsm_x2t(uint32_t a, uint32_t& r0, uint32_t& r1) {
    asm volatile("ldmatrix.sync.aligned.m8n8.x2.trans.shared.b16 {%0,%1}, [%2];"
                 : "=r"(r0), "=r"(r1) : "r"(a));
}
static __device__ __forceinline__ void mma16816(float* c, const uint32_t* a,
                                                uint32_t b0, uint32_t b1) {
    asm volatile("mma.sync.aligned.m16n8k16.row.col.f32.f16.f16.f32 "
                 "{%0,%1,%2,%3}, {%4,%5,%6,%7}, {%8,%9}, {%0,%1,%2,%3};"
                 : "+f"(c[0]), "+f"(c[1]), "+f"(c[2]), "+f"(c[3])
                 : "r"(a[0]), "r"(a[1]), "r"(a[2]), "r"(a[3]), "r"(b0), "r"(b1));
}

// ---- FFMA-pipe exp (valid for x <= ~0; clamps hard underflow) ----
static __device__ __forceinline__ float fexp(float x) {
    float t = x * 1.4426950408889634f;
    t = fmaxf(t, -125.0f);
    float r = t + 12582912.0f;
    float fi = r - 12582912.0f;
    float f = t - fi;
    int i = (int)fi;
    float p = 1.5403530393e-4f;
    p = fmaf(p, f, 1.3333558146e-3f);
    p = fmaf(p, f, 9.6181291076e-3f);
    p = fmaf(p, f, 5.5504108664e-2f);
    p = fmaf(p, f, 2.4022650696e-1f);
    p = fmaf(p, f, 6.9314718056e-1f);
    p = fmaf(p, f, 1.0f);
    return __int_as_float(__float_as_int(p) + (i << 23));
}

// ---- FFMA-pipe natural log (u > 0, normal) ----
static __device__ __forceinline__ float flog(float u) {
    int ib = __float_as_int(u);
    int e = (ib - 0x3f3504f3) >> 23;
    float m = __int_as_float(ib - (e << 23));
    float f = m - 1.0f;
    float z = f * f;
    float P = 7.0376836292e-2f;
    P = fmaf(P, f, -1.1514610310e-1f);
    P = fmaf(P, f, 1.1676998740e-1f);
    P = fmaf(P, f, -1.2420140846e-1f);
    P = fmaf(P, f, 1.4249322787e-1f);
    P = fmaf(P, f, -1.6668057665e-1f);
    P = fmaf(P, f, 2.0000714765e-1f);
    P = fmaf(P, f, -2.4999993993e-1f);
    P = fmaf(P, f, 3.3333331174e-1f);
    float rr = fmaf(P * z, f, fmaf(-0.5f, z, f));
    return fmaf((float)e, 0.69314718055994531f, rr);
}

static __device__ __forceinline__ float softplus_f(float v) {
    return fmaxf(v, 0.0f) + flog(1.0f + fexp(-fabsf(v)));
}

__global__ __launch_bounds__(NTHREADS, 1)
void nsc_hmma_kernel(const float* __restrict__ x, const float* __restrict__ c,
                     const float* __restrict__ W1, const float* __restrict__ b1,
                     const float* __restrict__ W2, const float* __restrict__ b2,
                     const float* __restrict__ W3, const float* __restrict__ b3,
                     float* __restrict__ out, int B, int ntiles)
{
    extern __shared__ char smb[];
    const uint32_t sb = smem_u32(smb);

    __half* hAh = (__half*)(smb + OFF_AH);
    __half* hAl = (__half*)(smb + OFF_AL);
    __half* hW2 = (__half*)(smb + OFF_W2);
    __half* hW3 = (__half*)(smb + OFF_W3);
    float* sP   = (float*)(smb + OFF_P);
    float* sIn  = (float*)(smb + OFF_IN);
    float* sLow = (float*)(smb + OFF_LOW);
    float* sW1  = (float*)(smb + OFF_W1);
    float* sB1  = (float*)(smb + OFF_B1);
    float* sB2  = (float*)(smb + OFF_B2);
    float* sB3  = (float*)(smb + OFF_B3);
    float* sLd  = (float*)(smb + OFF_LD);

    const int tid = threadIdx.x;
    const int warp = tid >> 5;          // 0..15
    const int lane = tid & 31;
    const int wm = warp >> 2;           // 0..3 -> m0 = wm*32
    const int wn = warp & 3;            // 0..3
    const int m0 = wm * 32;
    const int n0g2 = wn * 32;
    const int n0g3 = wn * 40;
    const int lr = lane & 15;
    const int lc = (lane >> 4) * 8;
    const int grow = lane >> 2;
    const int gcol = (lane & 3) * 2;

    // ---- one-time: stage W2 (temp, in P region) + W3 + small tensors ----
    for (int i = tid; i < HID * HID; i += NTHREADS) {
        int k = i >> 7, n = i & 127;
        hW2[k * W2ST + n] = __float2half_rn(W2[i]);
    }
    for (int i = tid; i < HID * W3ST; i += NTHREADS) {
        int k = i / W3ST, n = i - k * W3ST;
        hW3[i] = __float2half_rn((n < OUTD) ? W3[k * OUTD + n] : 0.0f);
    }
    for (int i = tid; i < 7 * HID; i += NTHREADS) sW1[i] = W1[i];
    if (tid < HID) { sB1[tid] = b1[tid]; sB2[tid] = b2[tid]; }
    if (tid < N3PAD) sB3[tid] = (tid < OUTD) ? b3[tid] : 0.0f;
    __syncthreads();

    // ---- one-time: persistent W2 B-fragments (64 regs/thread) ----
    uint32_t B2f[8][8];   // [kblk][n8idx*2 + {b0,b1}], n8idx 0..3 covers n0g2..n0g2+31
    #pragma unroll
    for (int ki = 0; ki < 8; ki++) {
        const int kb = ki * 16;
        #pragma unroll
        for (int np = 0; np < 2; np++) {
            uint32_t boff = (uint32_t)(((kb + lr) * W2ST + n0g2 + np * 16 + lc) * 2);
            ldsm_x4t(sb + OFF_W2 + boff, B2f[ki][np*4], B2f[ki][np*4+1],
                     B2f[ki][np*4+2], B2f[ki][np*4+3]);
        }
    }
    __syncthreads();   // W2 staging area now dead -> becomes P

    for (long tile = blockIdx.x; tile < ntiles; tile += gridDim.x) {
        const long base = tile * MROWS;
        const int nrows = (int)min((long)MROWS, (long)B - base);
        __syncthreads();

        // ---- stage inputs ----
        for (int i = tid; i < MROWS * XDIM; i += NTHREADS) {
            int r = i / XDIM, cc = i - r * XDIM;
            float v = (r < nrows) ? x[(base + r) * XDIM + cc] : 0.0f;
            if (cc < LOWERD) sLow[r * 4 + cc] = v;
            else             sIn[r * 8 + (cc - LOWERD)] = v;
        }
        for (int i = tid; i < MROWS * CDIM; i += NTHREADS) {
            int r = i >> 2, cc = i & 3;
            sIn[r * 8 + 3 + cc] = (r < nrows) ? c[(base + r) * CDIM + cc] : 0.0f;
        }
        __syncthreads();

        // ---- layer 1 (fp32) -> split fp16 A (h1 exact in hi+lo) ----
        for (int t = tid; t < MROWS * 64; t += NTHREADS) {
            int r = t >> 6, np = (t & 63) << 1;
            float a0 = sB1[np], a1 = sB1[np + 1];
            const float* inr = &sIn[r * 8];
            #pragma unroll
            for (int k = 0; k < 7; k++) {
                float iv = inr[k];
                a0 = fmaf(iv, sW1[k * HID + np], a0);
                a1 = fmaf(iv, sW1[k * HID + np + 1], a1);
            }
            a0 = fmaxf(a0, 0.0f); a1 = fmaxf(a1, 0.0f);
            __half h0 = __float2half_rn(a0), h1v = __float2half_rn(a1);
            __half l0 = __float2half_rn(a0 - __half2float(h0));
            __half l1 = __float2half_rn(a1 - __half2float(h1v));
            *(__half2*)&hAh[r * AST + np] = __halves2half2(h0, h1v);
            *(__half2*)&hAl[r * AST + np] = __halves2half2(l0, l1);
        }
        __syncthreads();

        // ---- GEMM2: warp tile 32x32, split-A, B in registers ----
        float acc2[2][4][4];
        #pragma unroll
        for (int ms = 0; ms < 2; ms++)
            #pragma unroll
            for (int nb = 0; nb < 4; nb++)
                #pragma unroll
                for (int q = 0; q < 4; q++) acc2[ms][nb][q] = 0.0f;
        #pragma unroll
        for (int ki = 0; ki < 8; ki++) {
            const int kb = ki * 16;
            #pragma unroll
            for (int ms = 0; ms < 2; ms++) {
                uint32_t ah[4], al[4];
                uint32_t aoff = (uint32_t)(((m0 + ms * 16 + lr) * AST + kb + lc) * 2);
                ldsm_x4(sb + OFF_AH + aoff, ah[0], ah[1], ah[2], ah[3]);
                ldsm_x4(sb + OFF_AL + aoff, al[0], al[1], al[2], al[3]);
                #pragma unroll
                for (int nb = 0; nb < 4; nb++)
                    mma16816(acc2[ms][nb], ah, B2f[ki][nb*2], B2f[ki][nb*2+1]);
                #pragma unroll
                for (int nb = 0; nb < 4; nb++)
                    mma16816(acc2[ms][nb], al, B2f[ki][nb*2], B2f[ki][nb*2+1]);
            }
        }
        __syncthreads();

        // ---- h2 = relu(D + b2) -> plain fp16 A (hi buffer only) ----
        #pragma unroll
        for (int ms = 0; ms < 2; ms++)
            #pragma unroll
            for (int nb = 0; nb < 4; nb++) {
                int col = n0g2 + nb * 8 + gcol;
                float bb0 = sB2[col], bb1 = sB2[col + 1];
                #pragma unroll
                for (int h = 0; h < 2; h++) {
                    int r = m0 + ms * 16 + grow + h * 8;
                    float v0 = fmaxf(acc2[ms][nb][2*h]   + bb0, 0.0f);
                    float v1 = fmaxf(acc2[ms][nb][2*h+1] + bb1, 0.0f);
                    *(__half2*)&hAh[r * AST + col] =
                        __halves2half2(__float2half_rn(v0), __float2half_rn(v1));
                }
            }
        __syncthreads();

        // ---- GEMM3: warp tile 32x40, plain-A, B from SMEM, k staggered ----
        {
            float acc3[2][5][4];
            #pragma unroll
            for (int ms = 0; ms < 2; ms++)
                #pragma unroll
                for (int nb = 0; nb < 5; nb++)
                    #pragma unroll
                    for (int q = 0; q < 4; q++) acc3[ms][nb][q] = 0.0f;
            #pragma unroll
            for (int ki = 0; ki < 8; ki++) {
                const int kb = ((ki + warp) & 7) * 16;
                uint32_t bb[4][4], be[2];
                #pragma unroll
                for (int np = 0; np < 2; np++) {
                    uint32_t boff = (uint32_t)(((kb + lr) * W3ST + n0g3 + np * 16 + lc) * 2);
                    ldsm_x4t(sb + OFF_W3 + boff, bb[np*2][0], bb[np*2][1],
                             bb[np*2+1][0], bb[np*2+1][1]);
                }
                {
                    uint32_t boff = (uint32_t)(((kb + lr) * W3ST + n0g3 + 32) * 2);
                    ldsm_x2t(sb + OFF_W3 + boff, be[0], be[1]);
                }
                #pragma unroll
                for (int ms = 0; ms < 2; ms++) {
                    uint32_t ah[4];
                    uint32_t aoff = (uint32_t)(((m0 + ms * 16 + lr) * AST + kb + lc) * 2);
                    ldsm_x4(sb + OFF_AH + aoff, ah[0], ah[1], ah[2], ah[3]);
                    #pragma unroll
                    for (int nb = 0; nb < 4; nb++)
                        mma16816(acc3[ms][nb], ah, bb[nb][0], bb[nb][1]);
                    mma16816(acc3[ms][4], ah, be[0], be[1]);
                }
            }
            // P = D + b3 (skip pad cols >= 144)
            #pragma unroll
            for (int ms = 0; ms < 2; ms++)
                #pragma unroll
                for (int nb = 0; nb < 5; nb++) {
                    int col = n0g3 + nb * 8 + gcol;
                    if (col < 144) {
                        float bb0 = sB3[col], bb1 = sB3[col + 1];
                        #pragma unroll
                        for (int h = 0; h < 2; h++) {
                            int r = m0 + ms * 16 + grow + h * 8;
                            sP[r * PST + col]     = acc3[ms][nb][2*h]   + bb0;
                            sP[r * PST + col + 1] = acc3[ms][nb][2*h+1] + bb1;
                        }
                    }
                }
        }
        __syncthreads();

        // ---- spline epilogue (FFMA-pipe transcendentals) ----
        if (tid < MROWS * LOWERD) {
            const int item = tid;
            const int r = item / 3;
            const int d = item - r * 3;
            const float* p = &sP[r * PST + d * SPLD];
            const float xv = sLow[r * 4 + d];
            const bool oob = (xv <= -BOUNDV) || (xv >= BOUNDV);
            const float xm = oob ? -BOUNDV : xv;

            float mW = -1e30f;
            #pragma unroll
            for (int i = 0; i < KNOTS; i++) mW = fmaxf(mW, p[i]);
            float ew[KNOTS], S = 0.0f;
            #pragma unroll
            for (int i = 0; i < KNOTS; i++) { ew[i] = fexp(p[i] - mW); S += ew[i]; }
            const float invS = __fdividef(2.0f * BOUNDV, S);

            int idx = 0; float cumex = 0.0f, wsel = ew[0];
            bool found = false; float cum = 0.0f;
            #pragma unroll
            for (int i = 0; i < KNOTS; i++) {
                float cn = cum + ew[i];
                bool take = (!found) && (xm < fmaf(cn, invS, -BOUNDV));
                if (take) { found = true; idx = i; cumex = cum; wsel = ew[i]; }
                cum = cn;
            }
            if (!found) { idx = KNOTS - 1; cumex = cum - ew[KNOTS - 1]; wsel = ew[KNOTS - 1]; }

            const float xk_b = fmaf(cumex, invS, -BOUNDV);
            const float wk   = wsel * invS;

            float mH = -1e30f;
            #pragma unroll
            for (int i = 0; i < KNOTS; i++) mH = fmaxf(mH, p[KNOTS + i]);
            float SH = 0.0f, cumh = 0.0f, hsel = 0.0f;
            #pragma unroll
            for (int i = 0; i < KNOTS; i++) {
                float e = fexp(p[KNOTS + i] - mH);
                SH += e;
                if (i < idx)  cumh += e;
                if (i == idx) hsel = e;
            }
            const float invSH = __fdividef(2.0f * BOUNDV, SH);
            const float yk_b = fmaf(cumh, invSH, -BOUNDV);
            const float hk   = hsel * invSH;

            float d0 = 1.0f, d1 = 1.0f;
            if (idx > 0)         d0 = softplus_f(p[2 * KNOTS + idx - 1]);
            if (idx < KNOTS - 1) d1 = softplus_f(p[2 * KNOTS + idx]);

            const float rwk = __fdividef(1.0f, wk);
            const float sk = hk * rwk;
            float relx = fminf(fmaxf((xm - xk_b) * rwk, 0.0f), 1.0f);
            const float omr = 1.0f - relx;
            const float r1 = relx * omr;
            const float den = sk + (d1 + d0 - 2.0f * sk) * r1;
            const float rden = __fdividef(1.0f, den);
            const float num = hk * (sk * relx * relx + d0 * r1);
            float y = yk_b + num * rden;
            const float arg = d1 * relx * relx + 2.0f * sk * r1 + d0 * omr * omr;
            float ld = flog(sk * sk * arg * rden * rden);
            if (oob) { y = xv; ld = 0.0f; }

            sLd[r * 4 + d] = ld;
            if (r < nrows) {
                out[(base + r) * XDIM + d] = y;
                out[(base + r) * XDIM + LOWERD + d] = sIn[r * 8 + d];
            }
        }
        __syncthreads();
        if (tid < MROWS && tid < nrows)
            out[(long)B * XDIM + base + tid] =
                sLd[tid * 4] + sLd[tid * 4 + 1] + sLd[tid * 4 + 2];
    }
}

extern "C" void kernel_launch(void* const* d_in, const int* in_sizes, int n_in,
                              void* d_out, int out_size)
{
    const float* x  = (const float*)d_in[0];
    const float* c  = (const float*)d_in[1];
    const float* W1 = (const float*)d_in[2];
    const float* b1 = (const float*)d_in[3];
    const float* W2 = (const float*)d_in[4];
    const float* b2 = (const float*)d_in[5];
    const float* W3 = (const float*)d_in[6];
    const float* b3 = (const float*)d_in[7];
    (void)n_in; (void)out_size;

    const int B = in_sizes[0] / XDIM;
    const int ntiles = (B + MROWS - 1) / MROWS;
    float* out = (float*)d_out;

    int sms = 148;
    cudaDeviceGetAttribute(&sms, cudaDevAttrMultiProcessorCount, 0);
    int grid = sms < ntiles ? sms : ntiles;

    cudaFuncSetAttribute(nsc_hmma_kernel, cudaFuncAttributeMaxDynamicSharedMemorySize,
                         SMEM_BYTES);
    nsc_hmma_kernel<<<grid, NTHREADS, SMEM_BYTES>>>(x, c, W1, b1, W2, b2, W3, b3,
                                                    out, B, ntiles);
}

// round 12
// speedup vs baseline: 1.2441x; 1.1472x over previous
#include <cuda_runtime.h>
#include <cuda_fp16.h>
#include <math.h>
#include <stdint.h>

#define KNOTS   16
#define BOUNDV  5.0f
#define XDIM    6
#define CDIM    4
#define HID     128
#define SPLD    47
#define LOWERD  3
#define OUTD    141
#define NPAD    144
#define MROWS   128
#define NTHREADS 512

#define AST   136   // A tile stride (halves)
#define W2ST  136
#define W3ST  152
#define PST   147   // P stride (floats)

// ---- smem byte offsets ----
#define OFF_AH   0                     // 34816  A fp16 [128][136]
#define OFF_W2   34816                 // 34816  W2 fp16 [k=128][n pad 136]
#define OFF_W3   69632                 // 38912  W3 fp16 [k=128][n pad 152]
#define OFF_P    108544                // 75264  P fp32 [128][147]
#define OFF_IN   183808                // 4096
#define OFF_LOW  187904                // 2048
#define OFF_W1   189952                // 3584
#define OFF_B1   193536                // 512
#define OFF_B2   194048                // 512
#define OFF_B3   194560                // 576
#define OFF_LD   195136                // 2048
#define SMEM_BYTES 197184

static __device__ __forceinline__ uint32_t smem_u32(const void* p) {
    uint32_t a;
    asm("{ .reg .u64 t; cvta.to.shared.u64 t, %1; cvt.u32.u64 %0, t; }" : "=r"(a) : "l"(p));
    return a;
}

static __device__ __forceinline__ void ldsm_x4(uint32_t a, uint32_t& r0, uint32_t& r1,
                                               uint32_t& r2, uint32_t& r3) {
    asm volatile("ldmatrix.sync.aligned.m8n8.x4.shared.b16 {%0,%1,%2,%3}, [%4];"
                 : "=r"(r0), "=r"(r1), "=r"(r2), "=r"(r3) : "r"(a));
}
static __device__ __forceinline__ void ldsm_x4t(uint32_t a, uint32_t& r0, uint32_t& r1,
                                                uint32_t& r2, uint32_t& r3) {
    asm volatile("ldmatrix.sync.aligned.m8n8.x4.trans.shared.b16 {%0,%1,%2,%3}, [%4];"
                 : "=r"(r0), "=r"(r1), "=r"(r2), "=r"(r3) : "r"(a));
}
static __device__ __forceinline__ void ldsm_x2t(uint32_t a, uint32_t& r0, uint32_t& r1) {
    asm volatile("ldmatrix.sync.aligned.m8n8.x2.trans.shared.b16 {%0,%1}, [%2];"
                 : "=r"(r0), "=r"(r1) : "r"(a));
}
static __device__ __forceinline__ void mma16816(float* c, const uint32_t* a,
                                                uint32_t b0, uint32_t b1) {
    asm volatile("mma.sync.aligned.m16n8k16.row.col.f32.f16.f16.f32 "
                 "{%0,%1,%2,%3}, {%4,%5,%6,%7}, {%8,%9}, {%0,%1,%2,%3};"
                 : "+f"(c[0]), "+f"(c[1]), "+f"(c[2]), "+f"(c[3])
                 : "r"(a[0]), "r"(a[1]), "r"(a[2]), "r"(a[3]), "r"(b0), "r"(b1));
}

// ---- FFMA-pipe exp (valid for x <= ~0; clamps hard underflow) ----
static __device__ __forceinline__ float fexp(float x) {
    float t = x * 1.4426950408889634f;
    t = fmaxf(t, -125.0f);
    float r = t + 12582912.0f;
    float fi = r - 12582912.0f;
    float f = t - fi;
    int i = (int)fi;
    float p = 1.5403530393e-4f;
    p = fmaf(p, f, 1.3333558146e-3f);
    p = fmaf(p, f, 9.6181291076e-3f);
    p = fmaf(p, f, 5.5504108664e-2f);
    p = fmaf(p, f, 2.4022650696e-1f);
    p = fmaf(p, f, 6.9314718056e-1f);
    p = fmaf(p, f, 1.0f);
    return __int_as_float(__float_as_int(p) + (i << 23));
}

// ---- FFMA-pipe natural log (u > 0, normal) ----
static __device__ __forceinline__ float flog(float u) {
    int ib = __float_as_int(u);
    int e = (ib - 0x3f3504f3) >> 23;
    float m = __int_as_float(ib - (e << 23));
    float f = m - 1.0f;
    float z = f * f;
    float P = 7.0376836292e-2f;
    P = fmaf(P, f, -1.1514610310e-1f);
    P = fmaf(P, f, 1.1676998740e-1f);
    P = fmaf(P, f, -1.2420140846e-1f);
    P = fmaf(P, f, 1.4249322787e-1f);
    P = fmaf(P, f, -1.6668057665e-1f);
    P = fmaf(P, f, 2.0000714765e-1f);
    P = fmaf(P, f, -2.4999993993e-1f);
    P = fmaf(P, f, 3.3333331174e-1f);
    float rr = fmaf(P * z, f, fmaf(-0.5f, z, f));
    return fmaf((float)e, 0.69314718055994531f, rr);
}

static __device__ __forceinline__ float softplus_f(float v) {
    return fmaxf(v, 0.0f) + flog(1.0f + fexp(-fabsf(v)));
}

__global__ __launch_bounds__(NTHREADS, 1)
void nsc_hmma_kernel(const float* __restrict__ x, const float* __restrict__ c,
                     const float* __restrict__ W1, const float* __restrict__ b1,
                     const float* __restrict__ W2, const float* __restrict__ b2,
                     const float* __restrict__ W3, const float* __restrict__ b3,
                     float* __restrict__ out, int B, int ntiles)
{
    extern __shared__ char smb[];
    const uint32_t sb = smem_u32(smb);

    __half* hAh = (__half*)(smb + OFF_AH);
    __half* hW2 = (__half*)(smb + OFF_W2);
    __half* hW3 = (__half*)(smb + OFF_W3);
    float* sP   = (float*)(smb + OFF_P);
    float* sIn  = (float*)(smb + OFF_IN);
    float* sLow = (float*)(smb + OFF_LOW);
    float* sW1  = (float*)(smb + OFF_W1);
    float* sB1  = (float*)(smb + OFF_B1);
    float* sB2  = (float*)(smb + OFF_B2);
    float* sB3  = (float*)(smb + OFF_B3);
    float* sLd  = (float*)(smb + OFF_LD);

    const int tid = threadIdx.x;
    const int warp = tid >> 5;
    const int lane = tid & 31;
    const int wm = warp >> 1;          // 0..7  -> m0 = wm*16
    const int wn = warp & 1;           // 0..1
    const int m0 = wm * 16;
    const int lr = lane & 15;
    const int lc = (lane >> 4) * 8;
    const int grow = lane >> 2;
    const int gcol = (lane & 3) * 2;

    // ---- one-time weight staging (per CTA) ----
    for (int i = tid; i < HID * HID; i += NTHREADS) {
        int k = i >> 7, n = i & 127;
        hW2[k * W2ST + n] = __float2half_rn(W2[i]);
    }
    for (int i = tid; i < HID * NPAD; i += NTHREADS) {
        int k = i / NPAD, n = i - k * NPAD;
        hW3[k * W3ST + n] = __float2half_rn((n < OUTD) ? W3[k * OUTD + n] : 0.0f);
    }
    for (int i = tid; i < 7 * HID; i += NTHREADS) sW1[i] = W1[i];
    if (tid < HID) { sB1[tid] = b1[tid]; sB2[tid] = b2[tid]; }
    if (tid < NPAD) sB3[tid] = (tid < OUTD) ? b3[tid] : 0.0f;

    for (long tile = blockIdx.x; tile < ntiles; tile += gridDim.x) {
        const long base = tile * MROWS;
        const int nrows = (int)min((long)MROWS, (long)B - base);
        __syncthreads();

        // ---- stage inputs ----
        for (int i = tid; i < MROWS * XDIM; i += NTHREADS) {
            int r = i / XDIM, cc = i - r * XDIM;
            float v = (r < nrows) ? x[(base + r) * XDIM + cc] : 0.0f;
            if (cc < LOWERD) sLow[r * 4 + cc] = v;
            else             sIn[r * 8 + (cc - LOWERD)] = v;
        }
        for (int i = tid; i < MROWS * CDIM; i += NTHREADS) {
            int r = i >> 2, cc = i & 3;
            sIn[r * 8 + 3 + cc] = (r < nrows) ? c[(base + r) * CDIM + cc] : 0.0f;
        }
        __syncthreads();

        // ---- layer 1 (fp32) -> plain fp16 A ----
        for (int t = tid; t < MROWS * 64; t += NTHREADS) {
            int r = t >> 6, np = (t & 63) << 1;
            float a0 = sB1[np], a1 = sB1[np + 1];
            const float* inr = &sIn[r * 8];
            #pragma unroll
            for (int k = 0; k < 7; k++) {
                float iv = inr[k];
                a0 = fmaf(iv, sW1[k * HID + np], a0);
                a1 = fmaf(iv, sW1[k * HID + np + 1], a1);
            }
            a0 = fmaxf(a0, 0.0f); a1 = fmaxf(a1, 0.0f);
            *(__half2*)&hAh[r * AST + np] =
                __halves2half2(__float2half_rn(a0), __float2half_rn(a1));
        }
        __syncthreads();

        // ---- GEMM2: 128x128x128, plain-A, warp tile 16x64, k staggered ----
        float acc[8][4];
        {
            #pragma unroll
            for (int nt = 0; nt < 8; nt++)
                #pragma unroll
                for (int q = 0; q < 4; q++) acc[nt][q] = 0.0f;
            const int n0 = wn * 64;
            #pragma unroll
            for (int ki = 0; ki < 8; ki++) {
                const int kb = ((ki + warp) & 7) * 16;   // stagger L1 bursts per warp
                uint32_t ah[4], bb[4][4];
                uint32_t aoff = (uint32_t)(((m0 + lr) * AST + kb + lc) * 2);
                ldsm_x4(sb + OFF_AH + aoff, ah[0], ah[1], ah[2], ah[3]);
                #pragma unroll
                for (int np = 0; np < 4; np++) {
                    uint32_t boff = (uint32_t)(((kb + lr) * W2ST + n0 + np * 16 + lc) * 2);
                    ldsm_x4t(sb + OFF_W2 + boff, bb[np][0], bb[np][1], bb[np][2], bb[np][3]);
                }
                #pragma unroll
                for (int np = 0; np < 4; np++)
                    #pragma unroll
                    for (int j = 0; j < 2; j++)
                        mma16816(acc[np * 2 + j], ah, bb[np][2 * j], bb[np][2 * j + 1]);
            }
        }
        __syncthreads();

        // ---- h2 = relu(D + b2) -> plain fp16 A (overwrite) ----
        {
            const int n0 = wn * 64;
            #pragma unroll
            for (int nt = 0; nt < 8; nt++) {
                int col = n0 + nt * 8 + gcol;
                float bb0 = sB2[col], bb1 = sB2[col + 1];
                #pragma unroll
                for (int h = 0; h < 2; h++) {
                    int r = m0 + grow + h * 8;
                    float v0 = fmaxf(acc[nt][2 * h]     + bb0, 0.0f);
                    float v1 = fmaxf(acc[nt][2 * h + 1] + bb1, 0.0f);
                    *(__half2*)&hAh[r * AST + col] =
                        __halves2half2(__float2half_rn(v0), __float2half_rn(v1));
                }
            }
        }
        __syncthreads();

        // ---- GEMM3: 128x144x128, plain-A, warp tile 16x72, k staggered ----
        {
            float a3[9][4];
            #pragma unroll
            for (int nt = 0; nt < 9; nt++)
                #pragma unroll
                for (int q = 0; q < 4; q++) a3[nt][q] = 0.0f;
            const int n0 = wn * 72;
            #pragma unroll
            for (int ki = 0; ki < 8; ki++) {
                const int kb = ((ki + warp) & 7) * 16;
                uint32_t ah[4], bb[4][4], be[2];
                uint32_t aoff = (uint32_t)(((m0 + lr) * AST + kb + lc) * 2);
                ldsm_x4(sb + OFF_AH + aoff, ah[0], ah[1], ah[2], ah[3]);
                #pragma unroll
                for (int np = 0; np < 4; np++) {
                    uint32_t boff = (uint32_t)(((kb + lr) * W3ST + n0 + np * 16 + lc) * 2);
                    ldsm_x4t(sb + OFF_W3 + boff, bb[np][0], bb[np][1], bb[np][2], bb[np][3]);
                }
                {
                    uint32_t boff = (uint32_t)(((kb + lr) * W3ST + n0 + 64) * 2);
                    ldsm_x2t(sb + OFF_W3 + boff, be[0], be[1]);
                }
                #pragma unroll
                for (int np = 0; np < 4; np++)
                    #pragma unroll
                    for (int j = 0; j < 2; j++)
                        mma16816(a3[np * 2 + j], ah, bb[np][2 * j], bb[np][2 * j + 1]);
                mma16816(a3[8], ah, be[0], be[1]);
            }
            #pragma unroll
            for (int nt = 0; nt < 9; nt++) {
                int col = n0 + nt * 8 + gcol;
                float bb0 = sB3[col], bb1 = sB3[col + 1];
                #pragma unroll
                for (int h = 0; h < 2; h++) {
                    int r = m0 + grow + h * 8;
                    sP[r * PST + col]     = a3[nt][2 * h]     + bb0;
                    sP[r * PST + col + 1] = a3[nt][2 * h + 1] + bb1;
                }
            }
        }
        __syncthreads();

        // ---- spline epilogue (FFMA-pipe transcendentals) ----
        if (tid < MROWS * LOWERD) {
            const int item = tid;
            const int r = item / 3;
            const int d = item - r * 3;
            const float* p = &sP[r * PST + d * SPLD];
            const float xv = sLow[r * 4 + d];
            const bool oob = (xv <= -BOUNDV) || (xv >= BOUNDV);
            const float xm = oob ? -BOUNDV : xv;

            float mW = -1e30f;
            #pragma unroll
            for (int i = 0; i < KNOTS; i++) mW = fmaxf(mW, p[i]);
            float ew[KNOTS], S = 0.0f;
            #pragma unroll
            for (int i = 0; i < KNOTS; i++) { ew[i] = fexp(p[i] - mW); S += ew[i]; }
            const float invS = __fdividef(2.0f * BOUNDV, S);

            int idx = 0; float cumex = 0.0f, wsel = ew[0];
            bool found = false; float cum = 0.0f;
            #pragma unroll
            for (int i = 0; i < KNOTS; i++) {
                float cn = cum + ew[i];
                bool take = (!found) && (xm < fmaf(cn, invS, -BOUNDV));
                if (take) { found = true; idx = i; cumex = cum; wsel = ew[i]; }
                cum = cn;
            }
            if (!found) { idx = KNOTS - 1; cumex = cum - ew[KNOTS - 1]; wsel = ew[KNOTS - 1]; }

            const float xk_b = fmaf(cumex, invS, -BOUNDV);
            const float wk   = wsel * invS;

            float mH = -1e30f;
            #pragma unroll
            for (int i = 0; i < KNOTS; i++) mH = fmaxf(mH, p[KNOTS + i]);
            float SH = 0.0f, cumh = 0.0f, hsel = 0.0f;
            #pragma unroll
            for (int i = 0; i < KNOTS; i++) {
                float e = fexp(p[KNOTS + i] - mH);
                SH += e;
                if (i < idx)  cumh += e;
                if (i == idx) hsel = e;
            }
            const float invSH = __fdividef(2.0f * BOUNDV, SH);
            const float yk_b = fmaf(cumh, invSH, -BOUNDV);
            const float hk   = hsel * invSH;

            float d0 = 1.0f, d1 = 1.0f;
            if (idx > 0)         d0 = softplus_f(p[2 * KNOTS + idx - 1]);
            if (idx < KNOTS - 1) d1 = softplus_f(p[2 * KNOTS + idx]);

            const float rwk = __fdividef(1.0f, wk);
            const float sk = hk * rwk;
            float relx = fminf(fmaxf((xm - xk_b) * rwk, 0.0f), 1.0f);
            const float omr = 1.0f - relx;
            const float r1 = relx * omr;
            const float den = sk + (d1 + d0 - 2.0f * sk) * r1;
            const float rden = __fdividef(1.0f, den);
            const float num = hk * (sk * relx * relx + d0 * r1);
            float y = yk_b + num * rden;
            const float arg = d1 * relx * relx + 2.0f * sk * r1 + d0 * omr * omr;
            float ld = flog(sk * sk * arg * rden * rden);
            if (oob) { y = xv; ld = 0.0f; }

            sLd[r * 4 + d] = ld;
            if (r < nrows) {
                out[(base + r) * XDIM + d] = y;
                out[(base + r) * XDIM + LOWERD + d] = sIn[r * 8 + d];
            }
        }
        __syncthreads();
        if (tid < MROWS && tid < nrows)
            out[(long)B * XDIM + base + tid] =
                sLd[tid * 4] + sLd[tid * 4 + 1] + sLd[tid * 4 + 2];
    }
}

extern "C" void kernel_launch(void* const* d_in, const int* in_sizes, int n_in,
                              void* d_out, int out_size)
{
    const float* x  = (const float*)d_in[0];
    const float* c  = (const float*)d_in[1];
    const float* W1 = (const float*)d_in[2];
    const float* b1 = (const float*)d_in[3];
    const float* W2 = (const float*)d_in[4];
    const float* b2 = (const float*)d_in[5];
    const float* W3 = (const float*)d_in[6];
    const float* b3 = (const float*)d_in[7];
    (void)n_in; (void)out_size;

    const int B = in_sizes[0] / XDIM;
    const int ntiles = (B + MROWS - 1) / MROWS;
    float* out = (float*)d_out;

    int sms = 148;
    cudaDeviceGetAttribute(&sms, cudaDevAttrMultiProcessorCount, 0);
    int grid = sms < ntiles ? sms : ntiles;

    cudaFuncSetAttribute(nsc_hmma_kernel, cudaFuncAttributeMaxDynamicSharedMemorySize,
                         SMEM_BYTES);
    nsc_hmma_kernel<<<grid, NTHREADS, SMEM_BYTES>>>(x, c, W1, b1, W2, b2, W3, b3,
                                                    out, B, ntiles);
}

// round 13
// speedup vs baseline: 1.5732x; 1.2645x over previous
#include <cuda_runtime.h>
#include <cuda_fp16.h>
#include <math.h>
#include <stdint.h>

#define KNOTS   16
#define BOUNDV  5.0f
#define XDIM    6
#define CDIM    4
#define HID     128
#define SPLD    47
#define LOWERD  3
#define OUTD    141
#define NPAD    144
#define MROWS   128
#define NTHREADS 512

#define AST   136   // A tile stride (halves)
#define W2ST  136
#define W3ST  152
#define A1ST  24    // layer-1 A tile stride (halves) -> 48B rows, conflict-free ldsm
#define W1ST  136   // stacked W1 fp16 stride (halves)
#define PST   147   // P stride (floats)

// ---- smem byte offsets ----
#define OFF_AH   0                     // 34816  A fp16 [128][136]
#define OFF_W2   34816                 // 34816  W2 fp16 [k=128][n pad 136]
#define OFF_W3   69632                 // 38912  W3 fp16 [k=128][n pad 152]
#define OFF_P    108544                // 75264  P fp32 [128][147]
#define OFF_IN   183808                // 4096   in[128][8]
#define OFF_LOW  187904                // 2048
#define OFF_A1   189952                // 6144   A1 fp16 [128][24] (in_hi | in_lo)
#define OFF_W1H  196096                // 4352   W1 stacked fp16 [16][136]
#define OFF_B1   200448                // 512
#define OFF_B2   200960                // 512
#define OFF_B3   201472                // 576
#define OFF_LD   202048                // 2048
#define SMEM_BYTES 204096

static __device__ __forceinline__ uint32_t smem_u32(const void* p) {
    uint32_t a;
    asm("{ .reg .u64 t; cvta.to.shared.u64 t, %1; cvt.u32.u64 %0, t; }" : "=r"(a) : "l"(p));
    return a;
}

static __device__ __forceinline__ void ldsm_x4(uint32_t a, uint32_t& r0, uint32_t& r1,
                                               uint32_t& r2, uint32_t& r3) {
    asm volatile("ldmatrix.sync.aligned.m8n8.x4.shared.b16 {%0,%1,%2,%3}, [%4];"
                 : "=r"(r0), "=r"(r1), "=r"(r2), "=r"(r3) : "r"(a));
}
static __device__ __forceinline__ void ldsm_x4t(uint32_t a, uint32_t& r0, uint32_t& r1,
                                                uint32_t& r2, uint32_t& r3) {
    asm volatile("ldmatrix.sync.aligned.m8n8.x4.trans.shared.b16 {%0,%1,%2,%3}, [%4];"
                 : "=r"(r0), "=r"(r1), "=r"(r2), "=r"(r3) : "r"(a));
}
static __device__ __forceinline__ void ldsm_x2t(uint32_t a, uint32_t& r0, uint32_t& r1) {
    asm volatile("ldmatrix.sync.aligned.m8n8.x2.trans.shared.b16 {%0,%1}, [%2];"
                 : "=r"(r0), "=r"(r1) : "r"(a));
}
static __device__ __forceinline__ void mma16816(float* c, const uint32_t* a,
                                                uint32_t b0, uint32_t b1) {
    asm volatile("mma.sync.aligned.m16n8k16.row.col.f32.f16.f16.f32 "
                 "{%0,%1,%2,%3}, {%4,%5,%6,%7}, {%8,%9}, {%0,%1,%2,%3};"
                 : "+f"(c[0]), "+f"(c[1]), "+f"(c[2]), "+f"(c[3])
                 : "r"(a[0]), "r"(a[1]), "r"(a[2]), "r"(a[3]), "r"(b0), "r"(b1));
}

// ---- FFMA-pipe exp (valid for x <= ~0; clamps hard underflow) ----
static __device__ __forceinline__ float fexp(float x) {
    float t = x * 1.4426950408889634f;
    t = fmaxf(t, -125.0f);
    float r = t + 12582912.0f;
    float fi = r - 12582912.0f;
    float f = t - fi;
    int i = (int)fi;
    float p = 1.5403530393e-4f;
    p = fmaf(p, f, 1.3333558146e-3f);
    p = fmaf(p, f, 9.6181291076e-3f);
    p = fmaf(p, f, 5.5504108664e-2f);
    p = fmaf(p, f, 2.4022650696e-1f);
    p = fmaf(p, f, 6.9314718056e-1f);
    p = fmaf(p, f, 1.0f);
    return __int_as_float(__float_as_int(p) + (i << 23));
}

// ---- FFMA-pipe natural log (u > 0, normal) ----
static __device__ __forceinline__ float flog(float u) {
    int ib = __float_as_int(u);
    int e = (ib - 0x3f3504f3) >> 23;
    float m = __int_as_float(ib - (e << 23));
    float f = m - 1.0f;
    float z = f * f;
    float P = 7.0376836292e-2f;
    P = fmaf(P, f, -1.1514610310e-1f);
    P = fmaf(P, f, 1.1676998740e-1f);
    P = fmaf(P, f, -1.2420140846e-1f);
    P = fmaf(P, f, 1.4249322787e-1f);
    P = fmaf(P, f, -1.6668057665e-1f);
    P = fmaf(P, f, 2.0000714765e-1f);
    P = fmaf(P, f, -2.4999993993e-1f);
    P = fmaf(P, f, 3.3333331174e-1f);
    float rr = fmaf(P * z, f, fmaf(-0.5f, z, f));
    return fmaf((float)e, 0.69314718055994531f, rr);
}

static __device__ __forceinline__ float softplus_f(float v) {
    return fmaxf(v, 0.0f) + flog(1.0f + fexp(-fabsf(v)));
}

__global__ __launch_bounds__(NTHREADS, 1)
void nsc_hmma_kernel(const float* __restrict__ x, const float* __restrict__ c,
                     const float* __restrict__ W1, const float* __restrict__ b1,
                     const float* __restrict__ W2, const float* __restrict__ b2,
                     const float* __restrict__ W3, const float* __restrict__ b3,
                     float* __restrict__ out, int B, int ntiles)
{
    extern __shared__ char smb[];
    const uint32_t sb = smem_u32(smb);

    __half* hAh = (__half*)(smb + OFF_AH);
    __half* hW2 = (__half*)(smb + OFF_W2);
    __half* hW3 = (__half*)(smb + OFF_W3);
    __half* hA1 = (__half*)(smb + OFF_A1);
    __half* hW1 = (__half*)(smb + OFF_W1H);
    float* sP   = (float*)(smb + OFF_P);
    float* sIn  = (float*)(smb + OFF_IN);
    float* sLow = (float*)(smb + OFF_LOW);
    float* sB1  = (float*)(smb + OFF_B1);
    float* sB2  = (float*)(smb + OFF_B2);
    float* sB3  = (float*)(smb + OFF_B3);
    float* sLd  = (float*)(smb + OFF_LD);

    const int tid = threadIdx.x;
    const int warp = tid >> 5;
    const int lane = tid & 31;
    const int wm = warp >> 1;          // 0..7  -> m0 = wm*16
    const int wn = warp & 1;           // 0..1
    const int m0 = wm * 16;
    const int lr = lane & 15;
    const int lc = (lane >> 4) * 8;
    const int grow = lane >> 2;
    const int gcol = (lane & 3) * 2;

    // ---- one-time weight staging (per CTA) ----
    for (int i = tid; i < HID * HID; i += NTHREADS) {
        int k = i >> 7, n = i & 127;
        hW2[k * W2ST + n] = __float2half_rn(W2[i]);
    }
    for (int i = tid; i < HID * NPAD; i += NTHREADS) {
        int k = i / NPAD, n = i - k * NPAD;
        hW3[k * W3ST + n] = __float2half_rn((n < OUTD) ? W3[k * OUTD + n] : 0.0f);
    }
    // W1 stacked twice: rows 0-6 = W1, row 7 = 0, rows 8-14 = W1, row 15 = 0
    for (int i = tid; i < 16 * W1ST; i += NTHREADS) {
        int k = i / W1ST, n = i - k * W1ST;
        int ks = k & 7;
        float v = (ks < 7 && n < HID) ? W1[ks * HID + n] : 0.0f;
        hW1[i] = __float2half_rn(v);
    }
    if (tid < HID) { sB1[tid] = b1[tid]; sB2[tid] = b2[tid]; }
    if (tid < NPAD) sB3[tid] = (tid < OUTD) ? b3[tid] : 0.0f;

    for (long tile = blockIdx.x; tile < ntiles; tile += gridDim.x) {
        const long base = tile * MROWS;
        const int nrows = (int)min((long)MROWS, (long)B - base);
        __syncthreads();

        // ---- stage inputs ----
        for (int i = tid; i < MROWS * XDIM; i += NTHREADS) {
            int r = i / XDIM, cc = i - r * XDIM;
            float v = (r < nrows) ? x[(base + r) * XDIM + cc] : 0.0f;
            if (cc < LOWERD) sLow[r * 4 + cc] = v;
            else             sIn[r * 8 + (cc - LOWERD)] = v;
        }
        for (int i = tid; i < MROWS * CDIM; i += NTHREADS) {
            int r = i >> 2, cc = i & 3;
            sIn[r * 8 + 3 + cc] = (r < nrows) ? c[(base + r) * CDIM + cc] : 0.0f;
        }
        __syncthreads();

        // ---- stage A1: input hi/lo split fp16 [128][16] ----
        for (int i = tid; i < MROWS * 8; i += NTHREADS) {
            int r = i >> 3, k = i & 7;
            float v = (k < 7) ? sIn[r * 8 + k] : 0.0f;
            __half hi = __float2half_rn(v);
            __half lo = __float2half_rn(v - __half2float(hi));
            hA1[r * A1ST + k] = hi;
            hA1[r * A1ST + 8 + k] = lo;
        }
        __syncthreads();

        // ---- layer 1 via MMA: h1 = relu(in @ W1 + b1) -> fp16 A ----
        {
            float acc[8][4];
            #pragma unroll
            for (int nt = 0; nt < 8; nt++)
                #pragma unroll
                for (int q = 0; q < 4; q++) acc[nt][q] = 0.0f;
            const int n0 = wn * 64;
            uint32_t a1[4], bb[4][4];
            uint32_t aoff = (uint32_t)(((m0 + lr) * A1ST + lc) * 2);
            ldsm_x4(sb + OFF_A1 + aoff, a1[0], a1[1], a1[2], a1[3]);
            #pragma unroll
            for (int np = 0; np < 4; np++) {
                uint32_t boff = (uint32_t)((lr * W1ST + n0 + np * 16 + lc) * 2);
                ldsm_x4t(sb + OFF_W1H + boff, bb[np][0], bb[np][1], bb[np][2], bb[np][3]);
            }
            #pragma unroll
            for (int np = 0; np < 4; np++)
                #pragma unroll
                for (int j = 0; j < 2; j++)
                    mma16816(acc[np * 2 + j], a1, bb[np][2 * j], bb[np][2 * j + 1]);
            // convert: relu(+b1) -> fp16 A tile
            #pragma unroll
            for (int nt = 0; nt < 8; nt++) {
                int col = n0 + nt * 8 + gcol;
                float bb0 = sB1[col], bb1 = sB1[col + 1];
                #pragma unroll
                for (int h = 0; h < 2; h++) {
                    int r = m0 + grow + h * 8;
                    float v0 = fmaxf(acc[nt][2 * h]     + bb0, 0.0f);
                    float v1 = fmaxf(acc[nt][2 * h + 1] + bb1, 0.0f);
                    *(__half2*)&hAh[r * AST + col] =
                        __halves2half2(__float2half_rn(v0), __float2half_rn(v1));
                }
            }
        }
        __syncthreads();

        // ---- GEMM2: 128x128x128, plain-A, warp tile 16x64, k staggered ----
        float acc[8][4];
        {
            #pragma unroll
            for (int nt = 0; nt < 8; nt++)
                #pragma unroll
                for (int q = 0; q < 4; q++) acc[nt][q] = 0.0f;
            const int n0 = wn * 64;
            #pragma unroll
            for (int ki = 0; ki < 8; ki++) {
                const int kb = ((ki + warp) & 7) * 16;   // stagger L1 bursts per warp
                uint32_t ah[4], bb[4][4];
                uint32_t aoff = (uint32_t)(((m0 + lr) * AST + kb + lc) * 2);
                ldsm_x4(sb + OFF_AH + aoff, ah[0], ah[1], ah[2], ah[3]);
                #pragma unroll
                for (int np = 0; np < 4; np++) {
                    uint32_t boff = (uint32_t)(((kb + lr) * W2ST + n0 + np * 16 + lc) * 2);
                    ldsm_x4t(sb + OFF_W2 + boff, bb[np][0], bb[np][1], bb[np][2], bb[np][3]);
                }
                #pragma unroll
                for (int np = 0; np < 4; np++)
                    #pragma unroll
                    for (int j = 0; j < 2; j++)
                        mma16816(acc[np * 2 + j], ah, bb[np][2 * j], bb[np][2 * j + 1]);
            }
        }
        __syncthreads();

        // ---- h2 = relu(D + b2) -> plain fp16 A (overwrite) ----
        {
            const int n0 = wn * 64;
            #pragma unroll
            for (int nt = 0; nt < 8; nt++) {
                int col = n0 + nt * 8 + gcol;
                float bb0 = sB2[col], bb1 = sB2[col + 1];
                #pragma unroll
                for (int h = 0; h < 2; h++) {
                    int r = m0 + grow + h * 8;
                    float v0 = fmaxf(acc[nt][2 * h]     + bb0, 0.0f);
                    float v1 = fmaxf(acc[nt][2 * h + 1] + bb1, 0.0f);
                    *(__half2*)&hAh[r * AST + col] =
                        __halves2half2(__float2half_rn(v0), __float2half_rn(v1));
                }
            }
        }
        __syncthreads();

        // ---- GEMM3: 128x144x128, plain-A, warp tile 16x72, k staggered ----
        {
            float a3[9][4];
            #pragma unroll
            for (int nt = 0; nt < 9; nt++)
                #pragma unroll
                for (int q = 0; q < 4; q++) a3[nt][q] = 0.0f;
            const int n0 = wn * 72;
            #pragma unroll
            for (int ki = 0; ki < 8; ki++) {
                const int kb = ((ki + warp) & 7) * 16;
                uint32_t ah[4], bb[4][4], be[2];
                uint32_t aoff = (uint32_t)(((m0 + lr) * AST + kb + lc) * 2);
                ldsm_x4(sb + OFF_AH + aoff, ah[0], ah[1], ah[2], ah[3]);
                #pragma unroll
                for (int np = 0; np < 4; np++) {
                    uint32_t boff = (uint32_t)(((kb + lr) * W3ST + n0 + np * 16 + lc) * 2);
                    ldsm_x4t(sb + OFF_W3 + boff, bb[np][0], bb[np][1], bb[np][2], bb[np][3]);
                }
                {
                    uint32_t boff = (uint32_t)(((kb + lr) * W3ST + n0 + 64) * 2);
                    ldsm_x2t(sb + OFF_W3 + boff, be[0], be[1]);
                }
                #pragma unroll
                for (int np = 0; np < 4; np++)
                    #pragma unroll
                    for (int j = 0; j < 2; j++)
                        mma16816(a3[np * 2 + j], ah, bb[np][2 * j], bb[np][2 * j + 1]);
                mma16816(a3[8], ah, be[0], be[1]);
            }
            #pragma unroll
            for (int nt = 0; nt < 9; nt++) {
                int col = n0 + nt * 8 + gcol;
                float bb0 = sB3[col], bb1 = sB3[col + 1];
                #pragma unroll
                for (int h = 0; h < 2; h++) {
                    int r = m0 + grow + h * 8;
                    sP[r * PST + col]     = a3[nt][2 * h]     + bb0;
                    sP[r * PST + col + 1] = a3[nt][2 * h + 1] + bb1;
                }
            }
        }
        __syncthreads();

        // ---- spline epilogue (FFMA-pipe transcendentals) ----
        if (tid < MROWS * LOWERD) {
            const int item = tid;
            const int r = item / 3;
            const int d = item - r * 3;
            const float* p = &sP[r * PST + d * SPLD];
            const float xv = sLow[r * 4 + d];
            const bool oob = (xv <= -BOUNDV) || (xv >= BOUNDV);
            const float xm = oob ? -BOUNDV : xv;

            float mW = -1e30f;
            #pragma unroll
            for (int i = 0; i < KNOTS; i++) mW = fmaxf(mW, p[i]);
            float ew[KNOTS], S = 0.0f;
            #pragma unroll
            for (int i = 0; i < KNOTS; i++) { ew[i] = fexp(p[i] - mW); S += ew[i]; }
            const float invS = __fdividef(2.0f * BOUNDV, S);

            int idx = 0; float cumex = 0.0f, wsel = ew[0];
            bool found = false; float cum = 0.0f;
            #pragma unroll
            for (int i = 0; i < KNOTS; i++) {
                float cn = cum + ew[i];
                bool take = (!found) && (xm < fmaf(cn, invS, -BOUNDV));
                if (take) { found = true; idx = i; cumex = cum; wsel = ew[i]; }
                cum = cn;
            }
            if (!found) { idx = KNOTS - 1; cumex = cum - ew[KNOTS - 1]; wsel = ew[KNOTS - 1]; }

            const float xk_b = fmaf(cumex, invS, -BOUNDV);
            const float wk   = wsel * invS;

            float mH = -1e30f;
            #pragma unroll
            for (int i = 0; i < KNOTS; i++) mH = fmaxf(mH, p[KNOTS + i]);
            float SH = 0.0f, cumh = 0.0f, hsel = 0.0f;
            #pragma unroll
            for (int i = 0; i < KNOTS; i++) {
                float e = fexp(p[KNOTS + i] - mH);
                SH += e;
                if (i < idx)  cumh += e;
                if (i == idx) hsel = e;
            }
            const float invSH = __fdividef(2.0f * BOUNDV, SH);
            const float yk_b = fmaf(cumh, invSH, -BOUNDV);
            const float hk   = hsel * invSH;

            float d0 = 1.0f, d1 = 1.0f;
            if (idx > 0)         d0 = softplus_f(p[2 * KNOTS + idx - 1]);
            if (idx < KNOTS - 1) d1 = softplus_f(p[2 * KNOTS + idx]);

            const float rwk = __fdividef(1.0f, wk);
            const float sk = hk * rwk;
            float relx = fminf(fmaxf((xm - xk_b) * rwk, 0.0f), 1.0f);
            const float omr = 1.0f - relx;
            const float r1 = relx * omr;
            const float den = sk + (d1 + d0 - 2.0f * sk) * r1;
            const float rden = __fdividef(1.0f, den);
            const float num = hk * (sk * relx * relx + d0 * r1);
            float y = yk_b + num * rden;
            const float arg = d1 * relx * relx + 2.0f * sk * r1 + d0 * omr * omr;
            float ld = flog(sk * sk * arg * rden * rden);
            if (oob) { y = xv; ld = 0.0f; }

            sLd[r * 4 + d] = ld;
            if (r < nrows) {
                out[(base + r) * XDIM + d] = y;
                out[(base + r) * XDIM + LOWERD + d] = sIn[r * 8 + d];
            }
        }
        __syncthreads();
        if (tid < MROWS && tid < nrows)
            out[(long)B * XDIM + base + tid] =
                sLd[tid * 4] + sLd[tid * 4 + 1] + sLd[tid * 4 + 2];
    }
}

extern "C" void kernel_launch(void* const* d_in, const int* in_sizes, int n_in,
                              void* d_out, int out_size)
{
    const float* x  = (const float*)d_in[0];
    const float* c  = (const float*)d_in[1];
    const float* W1 = (const float*)d_in[2];
    const float* b1 = (const float*)d_in[3];
    const float* W2 = (const float*)d_in[4];
    const float* b2 = (const float*)d_in[5];
    const float* W3 = (const float*)d_in[6];
    const float* b3 = (const float*)d_in[7];
    (void)n_in; (void)out_size;

    const int B = in_sizes[0] / XDIM;
    const int ntiles = (B + MROWS - 1) / MROWS;
    float* out = (float*)d_out;

    int sms = 148;
    cudaDeviceGetAttribute(&sms, cudaDevAttrMultiProcessorCount, 0);
    int grid = sms < ntiles ? sms : ntiles;

    cudaFuncSetAttribute(nsc_hmma_kernel, cudaFuncAttributeMaxDynamicSharedMemorySize,
                         SMEM_BYTES);
    nsc_hmma_kernel<<<grid, NTHREADS, SMEM_BYTES>>>(x, c, W1, b1, W2, b2, W3, b3,
                                                    out, B, ntiles);
}

// round 14
// speedup vs baseline: 1.6201x; 1.0298x over previous
#include <cuda_runtime.h>
#include <cuda_fp16.h>
#include <math.h>
#include <stdint.h>

#define KNOTS   16
#define BOUNDV  5.0f
#define XDIM    6
#define CDIM    4
#define HID     128
#define SPLD    47
#define LOWERD  3
#define OUTD    141
#define N3PAD   160     // GEMM3 padded n-space: [48|48|48|16], pads at q=47 of each block
#define MROWS   128
#define NTHREADS 512

#define AST   136   // A tile stride (halves)
#define W2ST  136
#define W3ST  168   // 160 data + 8 pad (halves), conflict-free ldsm rows
#define A1ST  24    // layer-1 A tile stride (halves)
#define W1ST  136
#define PST   164   // P stride (floats); blocks at d*48, 16B-aligned

// ---- smem byte offsets ----
#define OFF_AH   0                     // 34816
#define OFF_W2   34816                 // 34816
#define OFF_W3   69632                 // 43008
#define OFF_P    112640                // 83968  P fp32 [128][164]
#define OFF_IN   196608                // 4096
#define OFF_LOW  200704                // 2048
#define OFF_A1   202752                // 6144
#define OFF_W1H  208896                // 4352
#define OFF_B1   213248                // 512
#define OFF_B2   213760                // 512
#define OFF_B3   214272                // 640 (160 floats, padded layout)
#define OFF_LD   214912                // 2048
#define SMEM_BYTES 216960

static __device__ __forceinline__ uint32_t smem_u32(const void* p) {
    uint32_t a;
    asm("{ .reg .u64 t; cvta.to.shared.u64 t, %1; cvt.u32.u64 %0, t; }" : "=r"(a) : "l"(p));
    return a;
}

static __device__ __forceinline__ void ldsm_x4(uint32_t a, uint32_t& r0, uint32_t& r1,
                                               uint32_t& r2, uint32_t& r3) {
    asm volatile("ldmatrix.sync.aligned.m8n8.x4.shared.b16 {%0,%1,%2,%3}, [%4];"
                 : "=r"(r0), "=r"(r1), "=r"(r2), "=r"(r3) : "r"(a));
}
static __device__ __forceinline__ void ldsm_x4t(uint32_t a, uint32_t& r0, uint32_t& r1,
                                                uint32_t& r2, uint32_t& r3) {
    asm volatile("ldmatrix.sync.aligned.m8n8.x4.trans.shared.b16 {%0,%1,%2,%3}, [%4];"
                 : "=r"(r0), "=r"(r1), "=r"(r2), "=r"(r3) : "r"(a));
}
static __device__ __forceinline__ void mma16816(float* c, const uint32_t* a,
                                                uint32_t b0, uint32_t b1) {
    asm volatile("mma.sync.aligned.m16n8k16.row.col.f32.f16.f16.f32 "
                 "{%0,%1,%2,%3}, {%4,%5,%6,%7}, {%8,%9}, {%0,%1,%2,%3};"
                 : "+f"(c[0]), "+f"(c[1]), "+f"(c[2]), "+f"(c[3])
                 : "r"(a[0]), "r"(a[1]), "r"(a[2]), "r"(a[3]), "r"(b0), "r"(b1));
}

// ---- FFMA-pipe exp (args bounded |x| << 88; clamps hard underflow) ----
static __device__ __forceinline__ float fexp(float x) {
    float t = x * 1.4426950408889634f;
    t = fmaxf(t, -125.0f);
    float r = t + 12582912.0f;
    float fi = r - 12582912.0f;
    float f = t - fi;
    int i = (int)fi;
    float p = 1.5403530393e-4f;
    p = fmaf(p, f, 1.3333558146e-3f);
    p = fmaf(p, f, 9.6181291076e-3f);
    p = fmaf(p, f, 5.5504108664e-2f);
    p = fmaf(p, f, 2.4022650696e-1f);
    p = fmaf(p, f, 6.9314718056e-1f);
    p = fmaf(p, f, 1.0f);
    return __int_as_float(__float_as_int(p) + (i << 23));
}

static __device__ __forceinline__ float flog(float u) {
    int ib = __float_as_int(u);
    int e = (ib - 0x3f3504f3) >> 23;
    float m = __int_as_float(ib - (e << 23));
    float f = m - 1.0f;
    float z = f * f;
    float P = 7.0376836292e-2f;
    P = fmaf(P, f, -1.1514610310e-1f);
    P = fmaf(P, f, 1.1676998740e-1f);
    P = fmaf(P, f, -1.2420140846e-1f);
    P = fmaf(P, f, 1.4249322787e-1f);
    P = fmaf(P, f, -1.6668057665e-1f);
    P = fmaf(P, f, 2.0000714765e-1f);
    P = fmaf(P, f, -2.4999993993e-1f);
    P = fmaf(P, f, 3.3333331174e-1f);
    float rr = fmaf(P * z, f, fmaf(-0.5f, z, f));
    return fmaf((float)e, 0.69314718055994531f, rr);
}

static __device__ __forceinline__ float softplus_f(float v) {
    return fmaxf(v, 0.0f) + flog(1.0f + fexp(-fabsf(v)));
}

__global__ __launch_bounds__(NTHREADS, 1)
void nsc_hmma_kernel(const float* __restrict__ x, const float* __restrict__ c,
                     const float* __restrict__ W1, const float* __restrict__ b1,
                     const float* __restrict__ W2, const float* __restrict__ b2,
                     const float* __restrict__ W3, const float* __restrict__ b3,
                     float* __restrict__ out, int B, int ntiles)
{
    extern __shared__ char smb[];
    const uint32_t sb = smem_u32(smb);

    __half* hAh = (__half*)(smb + OFF_AH);
    __half* hW2 = (__half*)(smb + OFF_W2);
    __half* hW3 = (__half*)(smb + OFF_W3);
    __half* hA1 = (__half*)(smb + OFF_A1);
    __half* hW1 = (__half*)(smb + OFF_W1H);
    float* sP   = (float*)(smb + OFF_P);
    float* sIn  = (float*)(smb + OFF_IN);
    float* sLow = (float*)(smb + OFF_LOW);
    float* sB1  = (float*)(smb + OFF_B1);
    float* sB2  = (float*)(smb + OFF_B2);
    float* sB3  = (float*)(smb + OFF_B3);
    float* sLd  = (float*)(smb + OFF_LD);

    const int tid = threadIdx.x;
    const int warp = tid >> 5;
    const int lane = tid & 31;
    const int wm = warp >> 1;          // 0..7  -> m0 = wm*16
    const int wn = warp & 1;           // 0..1
    const int m0 = wm * 16;
    const int lr = lane & 15;
    const int lc = (lane >> 4) * 8;
    const int grow = lane >> 2;
    const int gcol = (lane & 3) * 2;

    // ---- one-time weight staging ----
    for (int i = tid; i < HID * HID; i += NTHREADS) {
        int k = i >> 7, n = i & 127;
        hW2[k * W2ST + n] = __float2half_rn(W2[i]);
    }
    // W3 staged in padded n-space [48|48|48|16]: col n -> orig b*47+q (b=n/48,q=n%48)
    for (int i = tid; i < HID * W3ST; i += NTHREADS) {
        int k = i / W3ST, n = i - k * W3ST;
        float v = 0.0f;
        if (n < N3PAD) {
            int b = n / 48, q = n - b * 48;
            if (b < 3 && q < 47) v = W3[k * OUTD + b * 47 + q];
        }
        hW3[i] = __float2half_rn(v);
    }
    for (int i = tid; i < 16 * W1ST; i += NTHREADS) {
        int k = i / W1ST, n = i - k * W1ST;
        int ks = k & 7;
        float v = (ks < 7 && n < HID) ? W1[ks * HID + n] : 0.0f;
        hW1[i] = __float2half_rn(v);
    }
    if (tid < HID) { sB1[tid] = b1[tid]; sB2[tid] = b2[tid]; }
    if (tid < N3PAD) {
        int b = tid / 48, q = tid - b * 48;
        sB3[tid] = (b < 3 && q < 47) ? b3[b * 47 + q] : 0.0f;
    }

    for (long tile = blockIdx.x; tile < ntiles; tile += gridDim.x) {
        const long base = tile * MROWS;
        const int nrows = (int)min((long)MROWS, (long)B - base);
        __syncthreads();

        // ---- stage inputs (vectorized) ----
        if (tid < MROWS * 3) {
            int r = tid / 3, pr = tid - r * 3;
            float2 v = make_float2(0.0f, 0.0f);
            if (r < nrows) v = *(const float2*)&x[(base + r) * XDIM + pr * 2];
            if (pr == 0)      { sLow[r * 4]     = v.x; sLow[r * 4 + 1] = v.y; }
            else if (pr == 1) { sLow[r * 4 + 2] = v.x; sIn[r * 8]      = v.y; }
            else              { sIn[r * 8 + 1]  = v.x; sIn[r * 8 + 2]  = v.y; }
        } else if (tid < MROWS * 3 + MROWS) {
            int r = tid - MROWS * 3;
            float4 v = make_float4(0.0f, 0.0f, 0.0f, 0.0f);
            if (r < nrows) v = *(const float4*)&c[(base + r) * CDIM];
            sIn[r * 8 + 3] = v.x; sIn[r * 8 + 4] = v.y;
            sIn[r * 8 + 5] = v.z; sIn[r * 8 + 6] = v.w;
        }
        __syncthreads();

        // ---- A1 pack: input hi/lo split fp16, one pass ----
        {
            int r = tid >> 2, kp = tid & 3;
            float2 v = *(const float2*)&sIn[r * 8 + kp * 2];
            if (kp == 3) v.y = 0.0f;
            __half2 hi = __floats2half2_rn(v.x, v.y);
            float lx = v.x - __low2float(hi);
            float ly = v.y - __high2float(hi);
            __half2 lo = __floats2half2_rn(lx, ly);
            *(__half2*)&hA1[r * A1ST + kp * 2] = hi;
            *(__half2*)&hA1[r * A1ST + 8 + kp * 2] = lo;
        }
        __syncthreads();

        // ---- layer 1 via MMA -> fp16 A ----
        {
            float acc[8][4];
            #pragma unroll
            for (int nt = 0; nt < 8; nt++)
                #pragma unroll
                for (int q = 0; q < 4; q++) acc[nt][q] = 0.0f;
            const int n0 = wn * 64;
            uint32_t a1[4], bb[4][4];
            uint32_t aoff = (uint32_t)(((m0 + lr) * A1ST + lc) * 2);
            ldsm_x4(sb + OFF_A1 + aoff, a1[0], a1[1], a1[2], a1[3]);
            #pragma unroll
            for (int np = 0; np < 4; np++) {
                uint32_t boff = (uint32_t)((lr * W1ST + n0 + np * 16 + lc) * 2);
                ldsm_x4t(sb + OFF_W1H + boff, bb[np][0], bb[np][1], bb[np][2], bb[np][3]);
            }
            #pragma unroll
            for (int np = 0; np < 4; np++)
                #pragma unroll
                for (int j = 0; j < 2; j++)
                    mma16816(acc[np * 2 + j], a1, bb[np][2 * j], bb[np][2 * j + 1]);
            #pragma unroll
            for (int nt = 0; nt < 8; nt++) {
                int col = n0 + nt * 8 + gcol;
                float2 bv = *(const float2*)&sB1[col];
                #pragma unroll
                for (int h = 0; h < 2; h++) {
                    int r = m0 + grow + h * 8;
                    float v0 = fmaxf(acc[nt][2 * h]     + bv.x, 0.0f);
                    float v1 = fmaxf(acc[nt][2 * h + 1] + bv.y, 0.0f);
                    *(__half2*)&hAh[r * AST + col] = __floats2half2_rn(v0, v1);
                }
            }
        }
        __syncthreads();

        // ---- GEMM2: 128x128x128, warp tile 16x64, k staggered ----
        float acc[8][4];
        {
            #pragma unroll
            for (int nt = 0; nt < 8; nt++)
                #pragma unroll
                for (int q = 0; q < 4; q++) acc[nt][q] = 0.0f;
            const int n0 = wn * 64;
            #pragma unroll
            for (int ki = 0; ki < 8; ki++) {
                const int kb = ((ki + warp) & 7) * 16;
                uint32_t ah[4], bb[4][4];
                uint32_t aoff = (uint32_t)(((m0 + lr) * AST + kb + lc) * 2);
                ldsm_x4(sb + OFF_AH + aoff, ah[0], ah[1], ah[2], ah[3]);
                #pragma unroll
                for (int np = 0; np < 4; np++) {
                    uint32_t boff = (uint32_t)(((kb + lr) * W2ST + n0 + np * 16 + lc) * 2);
                    ldsm_x4t(sb + OFF_W2 + boff, bb[np][0], bb[np][1], bb[np][2], bb[np][3]);
                }
                #pragma unroll
                for (int np = 0; np < 4; np++)
                    #pragma unroll
                    for (int j = 0; j < 2; j++)
                        mma16816(acc[np * 2 + j], ah, bb[np][2 * j], bb[np][2 * j + 1]);
            }
        }
        __syncthreads();

        // ---- h2 = relu(D + b2) -> fp16 A ----
        {
            const int n0 = wn * 64;
            #pragma unroll
            for (int nt = 0; nt < 8; nt++) {
                int col = n0 + nt * 8 + gcol;
                float2 bv = *(const float2*)&sB2[col];
                #pragma unroll
                for (int h = 0; h < 2; h++) {
                    int r = m0 + grow + h * 8;
                    float v0 = fmaxf(acc[nt][2 * h]     + bv.x, 0.0f);
                    float v1 = fmaxf(acc[nt][2 * h + 1] + bv.y, 0.0f);
                    *(__half2*)&hAh[r * AST + col] = __floats2half2_rn(v0, v1);
                }
            }
        }
        __syncthreads();

        // ---- GEMM3: 128x160x128 (padded n), warp tile 16x80, k staggered ----
        {
            float a3[10][4];
            #pragma unroll
            for (int nt = 0; nt < 10; nt++)
                #pragma unroll
                for (int q = 0; q < 4; q++) a3[nt][q] = 0.0f;
            const int n0 = wn * 80;
            #pragma unroll
            for (int ki = 0; ki < 8; ki++) {
                const int kb = ((ki + warp) & 7) * 16;
                uint32_t ah[4], bb[5][4];
                uint32_t aoff = (uint32_t)(((m0 + lr) * AST + kb + lc) * 2);
                ldsm_x4(sb + OFF_AH + aoff, ah[0], ah[1], ah[2], ah[3]);
                #pragma unroll
                for (int np = 0; np < 5; np++) {
                    uint32_t boff = (uint32_t)(((kb + lr) * W3ST + n0 + np * 16 + lc) * 2);
                    ldsm_x4t(sb + OFF_W3 + boff, bb[np][0], bb[np][1], bb[np][2], bb[np][3]);
                }
                #pragma unroll
                for (int np = 0; np < 5; np++)
                    #pragma unroll
                    for (int j = 0; j < 2; j++)
                        mma16816(a3[np * 2 + j], ah, bb[np][2 * j], bb[np][2 * j + 1]);
            }
            // P = D + b3 (padded layout; pads stored harmlessly, never read)
            #pragma unroll
            for (int nt = 0; nt < 10; nt++) {
                int col = n0 + nt * 8 + gcol;
                float2 bv = *(const float2*)&sB3[col];
                #pragma unroll
                for (int h = 0; h < 2; h++) {
                    int r = m0 + grow + h * 8;
                    *(float2*)&sP[r * PST + col] =
                        make_float2(a3[nt][2 * h] + bv.x, a3[nt][2 * h + 1] + bv.y);
                }
            }
        }
        __syncthreads();

        // ---- spline epilogue (vectorized loads, no-max softmax) ----
        if (tid < MROWS * LOWERD) {
            const int r = tid / 3;
            const int d = tid - r * 3;
            const float* p = &sP[r * PST + d * 48];
            const float xv = sLow[r * 4 + d];
            const bool oob = (xv <= -BOUNDV) || (xv >= BOUNDV);
            const float xm = oob ? -BOUNDV : xv;

            float pw[16];
            {
                float4 q0 = *(const float4*)(p);
                float4 q1 = *(const float4*)(p + 4);
                float4 q2 = *(const float4*)(p + 8);
                float4 q3 = *(const float4*)(p + 12);
                pw[0]=q0.x; pw[1]=q0.y; pw[2]=q0.z; pw[3]=q0.w;
                pw[4]=q1.x; pw[5]=q1.y; pw[6]=q1.z; pw[7]=q1.w;
                pw[8]=q2.x; pw[9]=q2.y; pw[10]=q2.z; pw[11]=q2.w;
                pw[12]=q3.x; pw[13]=q3.y; pw[14]=q3.z; pw[15]=q3.w;
            }
            float ew[KNOTS], S = 0.0f;
            #pragma unroll
            for (int i = 0; i < KNOTS; i++) { ew[i] = fexp(pw[i]); S += ew[i]; }
            const float invS = __fdividef(2.0f * BOUNDV, S);

            int idx = 0; float cumex = 0.0f, wsel = ew[0];
            bool found = false; float cum = 0.0f;
            #pragma unroll
            for (int i = 0; i < KNOTS; i++) {
                float cn = cum + ew[i];
                bool take = (!found) && (xm < fmaf(cn, invS, -BOUNDV));
                if (take) { found = true; idx = i; cumex = cum; wsel = ew[i]; }
                cum = cn;
            }
            if (!found) { idx = KNOTS - 1; cumex = cum - ew[KNOTS - 1]; wsel = ew[KNOTS - 1]; }

            const float xk_b = fmaf(cumex, invS, -BOUNDV);
            const float wk   = wsel * invS;

            float ph[16];
            {
                float4 q0 = *(const float4*)(p + 16);
                float4 q1 = *(const float4*)(p + 20);
                float4 q2 = *(const float4*)(p + 24);
                float4 q3 = *(const float4*)(p + 28);
                ph[0]=q0.x; ph[1]=q0.y; ph[2]=q0.z; ph[3]=q0.w;
                ph[4]=q1.x; ph[5]=q1.y; ph[6]=q1.z; ph[7]=q1.w;
                ph[8]=q2.x; ph[9]=q2.y; ph[10]=q2.z; ph[11]=q2.w;
                ph[12]=q3.x; ph[13]=q3.y; ph[14]=q3.z; ph[15]=q3.w;
            }
            float SH = 0.0f, cumh = 0.0f, hsel = 0.0f;
            #pragma unroll
            for (int i = 0; i < KNOTS; i++) {
                float e = fexp(ph[i]);
                SH += e;
                if (i < idx)  cumh += e;
                if (i == idx) hsel = e;
            }
            const float invSH = __fdividef(2.0f * BOUNDV, SH);
            const float yk_b = fmaf(cumh, invSH, -BOUNDV);
            const float hk   = hsel * invSH;

            float d0 = 1.0f, d1 = 1.0f;
            if (idx > 0)         d0 = softplus_f(p[32 + idx - 1]);
            if (idx < KNOTS - 1) d1 = softplus_f(p[32 + idx]);

            const float rwk = __fdividef(1.0f, wk);
            const float sk = hk * rwk;
            float relx = fminf(fmaxf((xm - xk_b) * rwk, 0.0f), 1.0f);
            const float omr = 1.0f - relx;
            const float r1 = relx * omr;
            const float den = sk + (d1 + d0 - 2.0f * sk) * r1;
            const float rden = __fdividef(1.0f, den);
            const float num = hk * (sk * relx * relx + d0 * r1);
            float y = yk_b + num * rden;
            const float arg = d1 * relx * relx + 2.0f * sk * r1 + d0 * omr * omr;
            float ld = flog(sk * sk * arg * rden * rden);
            if (oob) { y = xv; ld = 0.0f; }

            sLd[r * 4 + d] = ld;
            if (r < nrows) {
                out[(base + r) * XDIM + d] = y;
                out[(base + r) * XDIM + LOWERD + d] = sIn[r * 8 + d];
            }
        }
        __syncthreads();
        if (tid < MROWS && tid < nrows)
            out[(long)B * XDIM + base + tid] =
                sLd[tid * 4] + sLd[tid * 4 + 1] + sLd[tid * 4 + 2];
    }
}

extern "C" void kernel_launch(void* const* d_in, const int* in_sizes, int n_in,
                              void* d_out, int out_size)
{
    const float* x  = (const float*)d_in[0];
    const float* c  = (const float*)d_in[1];
    const float* W1 = (const float*)d_in[2];
    const float* b1 = (const float*)d_in[3];
    const float* W2 = (const float*)d_in[4];
    const float* b2 = (const float*)d_in[5];
    const float* W3 = (const float*)d_in[6];
    const float* b3 = (const float*)d_in[7];
    (void)n_in; (void)out_size;

    const int B = in_sizes[0] / XDIM;
    const int ntiles = (B + MROWS - 1) / MROWS;
    float* out = (float*)d_out;

    int sms = 148;
    cudaDeviceGetAttribute(&sms, cudaDevAttrMultiProcessorCount, 0);
    int grid = sms < ntiles ? sms : ntiles;

    cudaFuncSetAttribute(nsc_hmma_kernel, cudaFuncAttributeMaxDynamicSharedMemorySize,
                         SMEM_BYTES);
    nsc_hmma_kernel<<<grid, NTHREADS, SMEM_BYTES>>>(x, c, W1, b1, W2, b2, W3, b3,
                                                    out, B, ntiles);
}